// round 15
// baseline (speedup 1.0000x reference)
#include <cuda_runtime.h>
#include <cuda.h>
#include <cuda_fp16.h>
#include <cstdint>
#include <cstddef>

#define HID    1024
#define INTER_ 2816
#define MAX_T  8192
#define NEXP   8
#define HI     ((size_t)HID * INTER_)        // 2,883,584 floats per expert matrix

// ---------------------------------------------------------------------------
// Scratch (static device globals; allocation-free rule)
// ---------------------------------------------------------------------------
__device__ __align__(128) __half g_xh[(size_t)MAX_T * HID];
__device__ __align__(128) __half g_wg[(size_t)NEXP * HID * INTER_];
__device__ __align__(128) __half g_wu[(size_t)NEXP * HID * INTER_];
__device__ __align__(128) __half g_wd[(size_t)NEXP * HID * INTER_];
__device__ __align__(128) __half g_inter[(size_t)MAX_T * INTER_];
// [15] = convert ticket; [2+e] = gate/up chunks done for expert e (e=1..7)
__device__ int g_flags[16];

// ---------------------------------------------------------------------------
// Helpers
// ---------------------------------------------------------------------------
__device__ __forceinline__ uint32_t smem_u32(const void* p) {
    uint32_t a;
    asm("{ .reg .u64 t; cvta.to.shared.u64 t, %1; cvt.u32.u64 %0, t; }" : "=r"(a) : "l"(p));
    return a;
}
__device__ __forceinline__ uint32_t f22u(float a, float b) {
    __half2 h = __floats2half2_rn(a, b);
    return *reinterpret_cast<uint32_t*>(&h);
}

#define CP_ASYNC(sm, gm) \
    asm volatile("cp.async.cg.shared.global [%0], [%1], 16;" :: "r"(sm), "l"(gm))
#define CP_COMMIT() asm volatile("cp.async.commit_group;" ::: "memory")
#define CP_WAIT2()  asm volatile("cp.async.wait_group 2;" ::: "memory")
// GEMM-warp-only barrier (warps 0..7); converter warps never participate.
#define GBAR() asm volatile("bar.sync 1, 256;" ::: "memory")

__device__ __forceinline__ void ldm_x4(uint32_t& r0, uint32_t& r1, uint32_t& r2,
                                       uint32_t& r3, uint32_t addr) {
    asm volatile("ldmatrix.sync.aligned.m8n8.x4.shared.b16 {%0,%1,%2,%3}, [%4];"
                 : "=r"(r0), "=r"(r1), "=r"(r2), "=r"(r3) : "r"(addr));
}
__device__ __forceinline__ void ldm_x4_trans(uint32_t& r0, uint32_t& r1, uint32_t& r2,
                                             uint32_t& r3, uint32_t addr) {
    asm volatile("ldmatrix.sync.aligned.m8n8.x4.trans.shared.b16 {%0,%1,%2,%3}, [%4];"
                 : "=r"(r0), "=r"(r1), "=r"(r2), "=r"(r3) : "r"(addr));
}
__device__ __forceinline__ void mma_f16(float* c, const uint32_t* a, const uint32_t* b) {
    asm volatile(
        "mma.sync.aligned.m16n8k16.row.col.f32.f16.f16.f32 "
        "{%0,%1,%2,%3}, {%4,%5,%6,%7}, {%8,%9}, {%0,%1,%2,%3};"
        : "+f"(c[0]), "+f"(c[1]), "+f"(c[2]), "+f"(c[3])
        : "r"(a[0]), "r"(a[1]), "r"(a[2]), "r"(a[3]), "r"(b[0]), "r"(b[1]));
}

// ---------------------------------------------------------------------------
// Tiling constants
// ---------------------------------------------------------------------------
#define BK        32
#define STAGES    4
#define ASTRIDE   40
#define BSTR_F    136
#define BSTR_D    264
#define TA_BYTES  (128 * ASTRIDE * 2)        // 10240
#define BF_BYTES  (BK * BSTR_F * 2)          // 8704
#define BD_BYTES  (BK * BSTR_D * 2)          // 16896
#define FS_STAGE  (TA_BYTES + 2 * BF_BYTES)  // 27648
#define DS_STAGE  (TA_BYTES + BD_BYTES)      // 27136

// ---------------------------------------------------------------------------
// Convert queue: expert-ordered gate/up chunks (e=1..7), then down chunks.
// Chunk = 32768 floats (128 KB fp32 read, 64 KB fp16 write, ~3us per warp).
// ---------------------------------------------------------------------------
#define CHUNK_FL  32768
#define CPM       88                          // chunks per matrix (HI/CHUNK_FL)
#define CPE       (2 * CPM)                   // 176 per expert (gate+up)
#define NCVT_GU   (7 * CPE)                   // 1232
#define NCVT      (NCVT_GU + NEXP * CPM)      // + 704 down = 1936
#define MAX_GRABS 2                           // lifetime-coupling cap per warp

// One warp converts one chunk: 4096 uint4 outputs, lane-strided, ILP-8.
__device__ void cvt_chunk_warp(const float* __restrict__ src,
                               __half* __restrict__ dst, int lane) {
    const float4* in = (const float4*)src;
    uint4* out = (uint4*)dst;
    #pragma unroll 1
    for (int base = lane; base < 4096; base += 256) {
        float4 va[8], vb[8];
        #pragma unroll
        for (int j = 0; j < 8; ++j) {
            int m = base + j * 32;
            va[j] = in[2 * m];
            vb[j] = in[2 * m + 1];
        }
        #pragma unroll
        for (int j = 0; j < 8; ++j) {
            uint4 o;
            o.x = f22u(va[j].x, va[j].y);
            o.y = f22u(va[j].z, va[j].w);
            o.z = f22u(vb[j].x, vb[j].y);
            o.w = f22u(vb[j].z, vb[j].w);
            out[base + j * 32] = o;
        }
    }
}

__device__ void convert_worker(const float* __restrict__ gate,
                               const float* __restrict__ up,
                               const float* __restrict__ down) {
    const int lane = threadIdx.x & 31;
    #pragma unroll 1
    for (int g = 0; g < MAX_GRABS; ++g) {
        int item = 0;
        if (lane == 0) item = atomicAdd(&g_flags[15], 1);
        item = __shfl_sync(0xffffffff, item, 0);
        if (item >= NCVT) return;
        if (item < NCVT_GU) {
            const int e = 1 + item / CPE;
            const int j = item % CPE;
            const size_t off = (size_t)e * HI + (size_t)(j % CPM) * CHUNK_FL;
            const float* src = (j < CPM ? gate : up) + off;
            __half*      dst = (j < CPM ? g_wg : g_wu) + off;
            cvt_chunk_warp(src, dst, lane);
            if (lane == 0) { __threadfence(); atomicAdd(&g_flags[2 + e], 1); }
        } else {
            const size_t off = (size_t)(item - NCVT_GU) * CHUNK_FL;
            cvt_chunk_warp(down + off, g_wd + off, lane);
        }
    }
}

// ---------------------------------------------------------------------------
// Bootstrap: zero flags; convert x + expert-0 gate/up (~13us serial prologue).
// ---------------------------------------------------------------------------
__global__ void bootstrap_cvt(const float* __restrict__ x,
                              const float* __restrict__ gate,
                              const float* __restrict__ up, int T) {
    if (blockIdx.x == 0 && blockIdx.y == 0 && threadIdx.x < 16)
        g_flags[threadIdx.x] = 0;
    const float* src;
    __half* dst;
    size_t n8;
    if (blockIdx.y == 0)      { src = x;    dst = g_xh; n8 = (size_t)T * HID / 8; }
    else if (blockIdx.y == 1) { src = gate; dst = g_wg; n8 = HI / 8; }
    else                      { src = up;   dst = g_wu; n8 = HI / 8; }
    size_t i  = (size_t)blockIdx.x * blockDim.x + threadIdx.x;
    size_t st = (size_t)gridDim.x * blockDim.x;
    const float4* in = (const float4*)src;
    uint4* out = (uint4*)dst;
    for (; i < n8; i += st) {
        float4 a = in[2 * i], b = in[2 * i + 1];
        uint4 v;
        v.x = f22u(a.x, a.y); v.y = f22u(a.z, a.w);
        v.z = f22u(b.x, b.y); v.w = f22u(b.z, b.w);
        out[i] = v;
    }
}

// ---------------------------------------------------------------------------
// Exact tile cover: linear m-tile id -> (expert, start, cnt, m0).
// ---------------------------------------------------------------------------
__device__ __forceinline__ bool map_tile(const int* __restrict__ tpe, int t,
                                         int& e, int& start, int& cnt, int& m0) {
    int rem = t, st = 0;
    #pragma unroll
    for (int i = 0; i < NEXP; ++i) {
        const int c = __ldg(&tpe[i]);
        const int nt = (c + 127) >> 7;
        if (rem < nt) { e = i; start = st; cnt = c; m0 = rem << 7; return true; }
        rem -= nt;
        st += c;
    }
    return false;
}

// ---------------------------------------------------------------------------
// GEMM tile loads
// ---------------------------------------------------------------------------
__device__ __forceinline__ void load_tileA(uint32_t sdst, const __half* g, size_t ld,
                                           int tid, int maxrow) {
    #pragma unroll
    for (int j = 0; j < 2; ++j) {
        int idx = tid + j * 256;
        int r = idx >> 2, c = idx & 3;
        int gr = (r < maxrow) ? r : 0;
        CP_ASYNC(sdst + (r * ASTRIDE + c * 8) * 2, g + (size_t)gr * ld + c * 8);
    }
}
__device__ __forceinline__ void load_tileBF(uint32_t sdst, const __half* g, size_t ld,
                                            int tid) {
    #pragma unroll
    for (int j = 0; j < 2; ++j) {
        int idx = tid + j * 256;
        int r = idx >> 4, c = idx & 15;
        CP_ASYNC(sdst + (r * BSTR_F + c * 8) * 2, g + (size_t)r * ld + c * 8);
    }
}
__device__ __forceinline__ void load_tileBD(uint32_t sdst, const __half* g, size_t ld,
                                            int tid) {
    #pragma unroll
    for (int j = 0; j < 4; ++j) {
        int idx = tid + j * 256;
        int r = idx >> 5, c = idx & 31;
        CP_ASYNC(sdst + (r * BSTR_D + c * 8) * 2, g + (size_t)r * ld + c * 8);
    }
}

// ---------------------------------------------------------------------------
// Fused gate/up compute stage
// ---------------------------------------------------------------------------
__device__ __forceinline__ void compute_stage_fused(
    uint32_t sbase, uint32_t aOff, uint32_t bOff,
    float cg[4][4][4], float cu[4][4][4])
{
    const uint32_t aA = sbase + aOff;
    const uint32_t aG = sbase + TA_BYTES + bOff;
    const uint32_t aU = aG + BF_BYTES;
    #pragma unroll
    for (int ks = 0; ks < 2; ++ks) {
        uint32_t a[4][4];
        #pragma unroll
        for (int mt = 0; mt < 4; ++mt)
            ldm_x4(a[mt][0], a[mt][1], a[mt][2], a[mt][3], aA + ks * 32 + mt * 1280);
        uint32_t bg[4][2], bu[4][2];
        const uint32_t ksb = ks * 16 * BSTR_F * 2;
        #pragma unroll
        for (int p = 0; p < 2; ++p) {
            ldm_x4_trans(bg[2*p][0], bg[2*p][1], bg[2*p+1][0], bg[2*p+1][1],
                         aG + ksb + p * 32);
            ldm_x4_trans(bu[2*p][0], bu[2*p][1], bu[2*p+1][0], bu[2*p+1][1],
                         aU + ksb + p * 32);
        }
        #pragma unroll
        for (int mt = 0; mt < 4; ++mt)
            #pragma unroll
            for (int nt = 0; nt < 4; ++nt) {
                mma_f16(cg[mt][nt], a[mt], bg[nt]);
                mma_f16(cu[mt][nt], a[mt], bu[nt]);
            }
    }
}

// ---------------------------------------------------------------------------
// Fused gate/up GEMM + SwiGLU with 2 capped converter warps per CTA.
// Grid: (INTER_/128, tile_cover) so wave 1 is expert-0 m-tiles.
// Block: 320 threads (tid 0..255 GEMM via named barrier 1; 256..319 convert).
// ---------------------------------------------------------------------------
__global__ __launch_bounds__(320, 1)
void fused_gate_up_cw(const __half* __restrict__ X, const __half* __restrict__ WG,
                      const __half* __restrict__ WU, __half* __restrict__ OUT,
                      const int* __restrict__ tpe,
                      const float* __restrict__ gate_raw,
                      const float* __restrict__ up_raw,
                      const float* __restrict__ down_raw)
{
    const int tid = threadIdx.x;
    if (tid >= 256) {                 // converter warps: <=2 chunks, then exit
        convert_worker(gate_raw, up_raw, down_raw);
        return;
    }

    int e, start, cnt, m0;
    if (!map_tile(tpe, blockIdx.y, e, start, cnt, m0)) return;
    const int rows = min(128, cnt - m0);
    const int n0 = blockIdx.x * 128;

    // Expert 0 converted by bootstrap (previous launch); e>0 wait on chunks.
    if (e > 0) {
        if (tid == 0) {
            volatile int* fl = g_flags;
            while (fl[2 + e] < CPE) __nanosleep(128);
        }
        asm volatile("membar.gl;" ::: "memory");
        GBAR();
    }

    extern __shared__ __half sm[];
    const uint32_t sb = smem_u32(sm);
    const int wid = tid >> 5, lane = tid & 31;
    const int wm = wid & 1, wn = wid >> 1;

    const __half* Ag = X  + (size_t)(start + m0) * HID;
    const __half* Gg = WG + (size_t)e * HI + n0;
    const __half* Ug = WU + (size_t)e * HI + n0;

    const uint32_t aOff = ((wm * 64 + (lane & 15)) * ASTRIDE + (lane >> 4) * 8) * 2;
    const uint32_t bRow = ((lane >> 3) & 1) * 8 + (lane & 7);
    const uint32_t bOff = (bRow * BSTR_F + wn * 32 + (lane >> 4) * 8) * 2;

    float cg[4][4][4], cu[4][4][4];
    #pragma unroll
    for (int a = 0; a < 4; ++a)
        #pragma unroll
        for (int b = 0; b < 4; ++b)
            #pragma unroll
            for (int c = 0; c < 4; ++c) { cg[a][b][c] = 0.f; cu[a][b][c] = 0.f; }

    const int niter = HID / BK;  // 32
    #pragma unroll
    for (int s = 0; s < STAGES - 1; ++s) {
        const uint32_t st = sb + s * FS_STAGE;
        load_tileA (st,                       Ag + s * BK, HID, tid, rows);
        load_tileBF(st + TA_BYTES,            Gg + (size_t)s * BK * INTER_, INTER_, tid);
        load_tileBF(st + TA_BYTES + BF_BYTES, Ug + (size_t)s * BK * INTER_, INTER_, tid);
        CP_COMMIT();
    }
    for (int i = 0; i < niter; ++i) {
        CP_WAIT2();
        GBAR();
        compute_stage_fused(sb + (i % STAGES) * FS_STAGE, aOff, bOff, cg, cu);
        const int nb = i + STAGES - 1;
        if (nb < niter) {
            const uint32_t st = sb + (nb % STAGES) * FS_STAGE;
            load_tileA (st,                       Ag + nb * BK, HID, tid, rows);
            load_tileBF(st + TA_BYTES,            Gg + (size_t)nb * BK * INTER_, INTER_, tid);
            load_tileBF(st + TA_BYTES + BF_BYTES, Ug + (size_t)nb * BK * INTER_, INTER_, tid);
        }
        CP_COMMIT();
    }

    // Epilogue: SwiGLU, fp16 RN, packed stores
    const int rbase = wm * 64 + (lane >> 2);
    const int cbase = n0 + wn * 32 + 2 * (lane & 3);
    #pragma unroll
    for (int mt = 0; mt < 4; ++mt) {
        #pragma unroll
        for (int nt = 0; nt < 4; ++nt) {
            const int r0 = rbase + mt * 16;
            const int c  = cbase + nt * 8;
            if (r0 < rows) {
                float a0 = cg[mt][nt][0], a1 = cg[mt][nt][1];
                uint32_t v = f22u(a0 / (1.f + __expf(-a0)) * cu[mt][nt][0],
                                  a1 / (1.f + __expf(-a1)) * cu[mt][nt][1]);
                *(uint32_t*)(OUT + (size_t)(start + m0 + r0) * INTER_ + c) = v;
            }
            if (r0 + 8 < rows) {
                float a2 = cg[mt][nt][2], a3 = cg[mt][nt][3];
                uint32_t v = f22u(a2 / (1.f + __expf(-a2)) * cu[mt][nt][2],
                                  a3 / (1.f + __expf(-a3)) * cu[mt][nt][3]);
                *(uint32_t*)(OUT + (size_t)(start + m0 + r0 + 8) * INTER_ + c) = v;
            }
        }
    }
}

// ---------------------------------------------------------------------------
// Down-proj GEMM (R14, unchanged): out(fp32) = inter @ down.
// ---------------------------------------------------------------------------
__device__ __forceinline__ void compute_stage_down(
    uint32_t sbase, uint32_t aOff, uint32_t bOff, float cc[4][8][4])
{
    const uint32_t aA = sbase + aOff;
    const uint32_t aB = sbase + TA_BYTES + bOff;
    #pragma unroll
    for (int ks = 0; ks < 2; ++ks) {
        uint32_t a[4][4];
        #pragma unroll
        for (int mt = 0; mt < 4; ++mt)
            ldm_x4(a[mt][0], a[mt][1], a[mt][2], a[mt][3], aA + ks * 32 + mt * 1280);
        uint32_t bf[8][2];
        const uint32_t ksb = ks * 16 * BSTR_D * 2;
        #pragma unroll
        for (int p = 0; p < 4; ++p)
            ldm_x4_trans(bf[2*p][0], bf[2*p][1], bf[2*p+1][0], bf[2*p+1][1],
                         aB + ksb + p * 32);
        #pragma unroll
        for (int mt = 0; mt < 4; ++mt)
            #pragma unroll
            for (int nt = 0; nt < 8; ++nt)
                mma_f16(cc[mt][nt], a[mt], bf[nt]);
    }
}

__global__ __launch_bounds__(256, 1)
void down_proj(const __half* __restrict__ X, const __half* __restrict__ WD,
               float* __restrict__ OUT, const int* __restrict__ tpe)
{
    int e, start, cnt, m0;
    if (!map_tile(tpe, blockIdx.x, e, start, cnt, m0)) return;
    const int rows = min(128, cnt - m0);
    const int n0 = blockIdx.y * 256;

    extern __shared__ __half sm[];
    const uint32_t sb = smem_u32(sm);
    const int tid = threadIdx.x, wid = tid >> 5, lane = tid & 31;
    const int wm = wid & 1, wn = wid >> 1;

    const __half* Ag = X  + (size_t)(start + m0) * INTER_;
    const __half* Bg = WD + (size_t)e * HI + n0;

    const uint32_t aOff = ((wm * 64 + (lane & 15)) * ASTRIDE + (lane >> 4) * 8) * 2;
    const uint32_t bRow = ((lane >> 3) & 1) * 8 + (lane & 7);
    const uint32_t bOff = (bRow * BSTR_D + wn * 64 + (lane >> 4) * 8) * 2;

    float cc[4][8][4];
    #pragma unroll
    for (int a = 0; a < 4; ++a)
        #pragma unroll
        for (int b = 0; b < 8; ++b)
            #pragma unroll
            for (int c = 0; c < 4; ++c) cc[a][b][c] = 0.f;

    const int niter = INTER_ / BK;  // 88
    #pragma unroll
    for (int s = 0; s < STAGES - 1; ++s) {
        const uint32_t st = sb + s * DS_STAGE;
        load_tileA (st,            Ag + s * BK, INTER_, tid, rows);
        load_tileBD(st + TA_BYTES, Bg + (size_t)s * BK * HID, HID, tid);
        CP_COMMIT();
    }
    for (int i = 0; i < niter; ++i) {
        CP_WAIT2();
        __syncthreads();
        compute_stage_down(sb + (i % STAGES) * DS_STAGE, aOff, bOff, cc);
        const int nb = i + STAGES - 1;
        if (nb < niter) {
            const uint32_t st = sb + (nb % STAGES) * DS_STAGE;
            load_tileA (st,            Ag + nb * BK, INTER_, tid, rows);
            load_tileBD(st + TA_BYTES, Bg + (size_t)nb * BK * HID, HID, tid);
        }
        CP_COMMIT();
    }

    const int rbase = wm * 64 + (lane >> 2);
    const int cbase = n0 + wn * 64 + 2 * (lane & 3);
    #pragma unroll
    for (int mt = 0; mt < 4; ++mt) {
        #pragma unroll
        for (int nt = 0; nt < 8; ++nt) {
            const int r0 = rbase + mt * 16;
            const int c  = cbase + nt * 8;
            if (r0 < rows) {
                float2 v = make_float2(cc[mt][nt][0], cc[mt][nt][1]);
                *reinterpret_cast<float2*>(OUT + (size_t)(start + m0 + r0) * HID + c) = v;
            }
            if (r0 + 8 < rows) {
                float2 v = make_float2(cc[mt][nt][2], cc[mt][nt][3]);
                *reinterpret_cast<float2*>(OUT + (size_t)(start + m0 + r0 + 8) * HID + c) = v;
            }
        }
    }
}

// ---------------------------------------------------------------------------
// Host side: single stream, three plain launches.
// ---------------------------------------------------------------------------
extern "C" void kernel_launch(void* const* d_in, const int* in_sizes, int n_in,
                              void* d_out, int out_size)
{
    const float* x    = (const float*)d_in[0];   // [T, H]
    const float* gate = (const float*)d_in[1];   // [E, H, I]
    const float* up   = (const float*)d_in[2];   // [E, H, I]
    const float* down = (const float*)d_in[3];   // [E, I, H]
    const int*   tpe  = (const int*)d_in[4];     // [E]
    float* out = (float*)d_out;                  // [T, H]

    const int T = in_sizes[0] / HID;

    __half *xh, *wg, *wu, *wd, *inter;
    cudaGetSymbolAddress((void**)&xh, g_xh);
    cudaGetSymbolAddress((void**)&wg, g_wg);
    cudaGetSymbolAddress((void**)&wu, g_wu);
    cudaGetSymbolAddress((void**)&wd, g_wd);
    cudaGetSymbolAddress((void**)&inter, g_inter);

    cudaFuncSetAttribute(fused_gate_up_cw, cudaFuncAttributeMaxDynamicSharedMemorySize,
                         STAGES * FS_STAGE);
    cudaFuncSetAttribute(down_proj, cudaFuncAttributeMaxDynamicSharedMemorySize,
                         STAGES * DS_STAGE);

    // 1) Bootstrap: flags=0; convert x + expert-0 gate/up (~13us).
    bootstrap_cvt<<<dim3(512, 3), 256>>>(x, gate, up, T);

    // 2) Fused GEMM with in-kernel capped converter warps.
    //    Grid (n, m): wave 1 = expert-0 m-tiles; queue drains expert-major.
    const int tcover = (T + 127) / 128 + NEXP;
    dim3 g1(INTER_ / 128, tcover);
    fused_gate_up_cw<<<g1, 320, STAGES * FS_STAGE>>>(xh, wg, wu, inter, tpe,
                                                     gate, up, down);

    // 3) Down projection (all converts drained before this kernel boundary).
    dim3 g2(tcover, HID / 256);
    down_proj<<<g2, 256, STAGES * DS_STAGE>>>(inter, wd, out, tpe);
}

// round 16
// speedup vs baseline: 1.0476x; 1.0476x over previous
#include <cuda_runtime.h>
#include <cuda.h>
#include <cuda_fp16.h>
#include <cstdint>
#include <cstddef>

#define HID    1024
#define INTER_ 2816
#define MAX_T  8192
#define NEXP   8
#define HI     ((size_t)HID * INTER_)

// ---------------------------------------------------------------------------
// Scratch (static device globals; allocation-free rule)
// Weights kept in NATIVE layout [E][K][N], converted to fp16.
// ---------------------------------------------------------------------------
__device__ __align__(128) __half g_xh[(size_t)MAX_T * HID];          // x fp16 [T][H]
__device__ __align__(128) __half g_wg[(size_t)NEXP * HID * INTER_];  // gate fp16 [E][H][I]
__device__ __align__(128) __half g_wu[(size_t)NEXP * HID * INTER_];  // up fp16   [E][H][I]
__device__ __align__(128) __half g_wd[(size_t)NEXP * HID * INTER_];  // down fp16 [E][I][H]
__device__ __align__(128) __half g_inter[(size_t)MAX_T * INTER_];    // [T][I]
__device__ int g_flags[2];   // [0] = convert ticket, [1] = fused tiles done

// ---------------------------------------------------------------------------
// Helpers
// ---------------------------------------------------------------------------
__device__ __forceinline__ uint32_t smem_u32(const void* p) {
    uint32_t a;
    asm("{ .reg .u64 t; cvta.to.shared.u64 t, %1; cvt.u32.u64 %0, t; }" : "=r"(a) : "l"(p));
    return a;
}
__device__ __forceinline__ uint32_t f22u(float a, float b) {
    __half2 h = __floats2half2_rn(a, b);
    return *reinterpret_cast<uint32_t*>(&h);
}

#define CP_ASYNC(sm, gm) \
    asm volatile("cp.async.cg.shared.global [%0], [%1], 16;" :: "r"(sm), "l"(gm))
#define CP_COMMIT() asm volatile("cp.async.commit_group;" ::: "memory")
#define CP_WAIT2()  asm volatile("cp.async.wait_group 2;" ::: "memory")

__device__ __forceinline__ void ldm_x4(uint32_t& r0, uint32_t& r1, uint32_t& r2,
                                       uint32_t& r3, uint32_t addr) {
    asm volatile("ldmatrix.sync.aligned.m8n8.x4.shared.b16 {%0,%1,%2,%3}, [%4];"
                 : "=r"(r0), "=r"(r1), "=r"(r2), "=r"(r3) : "r"(addr));
}
__device__ __forceinline__ void ldm_x4_trans(uint32_t& r0, uint32_t& r1, uint32_t& r2,
                                             uint32_t& r3, uint32_t addr) {
    asm volatile("ldmatrix.sync.aligned.m8n8.x4.trans.shared.b16 {%0,%1,%2,%3}, [%4];"
                 : "=r"(r0), "=r"(r1), "=r"(r2), "=r"(r3) : "r"(addr));
}
__device__ __forceinline__ void mma_f16(float* c, const uint32_t* a, const uint32_t* b) {
    asm volatile(
        "mma.sync.aligned.m16n8k16.row.col.f32.f16.f16.f32 "
        "{%0,%1,%2,%3}, {%4,%5,%6,%7}, {%8,%9}, {%0,%1,%2,%3};"
        : "+f"(c[0]), "+f"(c[1]), "+f"(c[2]), "+f"(c[3])
        : "r"(a[0]), "r"(a[1]), "r"(a[2]), "r"(a[3]), "r"(b[0]), "r"(b[1]));
}

// ---------------------------------------------------------------------------
// Pre-pass: fp32 -> fp16 RN for x, gate, up (down handled in fused tail).
// Block (0,0) also zeroes the flags used by the fused kernel.
// ---------------------------------------------------------------------------
__global__ void cvt_xgu_kernel(const float* __restrict__ x,
                               const float* __restrict__ gate,
                               const float* __restrict__ up, int T)
{
    if (blockIdx.x == 0 && blockIdx.y == 0 && threadIdx.x < 2)
        g_flags[threadIdx.x] = 0;
    const float* src;
    __half* dst;
    size_t n8;
    switch (blockIdx.y) {
        case 0:  src = x;    dst = g_xh; n8 = (size_t)T * HID / 8; break;
        case 1:  src = gate; dst = g_wg; n8 = (size_t)NEXP * HI / 8; break;
        default: src = up;   dst = g_wu; n8 = (size_t)NEXP * HI / 8; break;
    }
    size_t i  = (size_t)blockIdx.x * blockDim.x + threadIdx.x;
    size_t st = (size_t)gridDim.x * blockDim.x;
    const float4* in = (const float4*)src;
    uint4* out = (uint4*)dst;
    for (; i < n8; i += st) {
        float4 a = in[2 * i], b = in[2 * i + 1];
        uint4 v;
        v.x = f22u(a.x, a.y); v.y = f22u(a.z, a.w);
        v.z = f22u(b.x, b.y); v.w = f22u(b.z, b.w);
        out[i] = v;
    }
}

// ---------------------------------------------------------------------------
// Tiling constants (halves).
// ---------------------------------------------------------------------------
#define BK        32
#define STAGES    4
#define ASTRIDE   40
#define BSTR_F    136
#define BSTR_D    264
#define TA_BYTES  (128 * ASTRIDE * 2)        // 10240
#define BF_BYTES  (BK * BSTR_F * 2)          // 8704
#define BD_BYTES  (BK * BSTR_D * 2)          // 16896
#define FS_STAGE  (TA_BYTES + 2 * BF_BYTES)  // 27648
#define DS_STAGE  (TA_BYTES + BD_BYTES)      // 27136

// Down-convert tail queue: 32768-float chunks (128 KB fp32 read each).
#define CHUNK_FL  32768
#define NCHUNK    ((int)((size_t)NEXP * HI / CHUNK_FL))   // 704
#define NQ_TAIL   140    // qualify threshold: < 148 resident CTAs => no queued
                         // GEMM CTA can ever be delayed by a converter

__device__ __forceinline__ void load_tileA(uint32_t sdst, const __half* g, size_t ld,
                                           int tid, int maxrow) {
    #pragma unroll
    for (int j = 0; j < 2; ++j) {
        int idx = tid + j * 256;
        int r = idx >> 2, c = idx & 3;
        int gr = (r < maxrow) ? r : 0;
        CP_ASYNC(sdst + (r * ASTRIDE + c * 8) * 2, g + (size_t)gr * ld + c * 8);
    }
}
__device__ __forceinline__ void load_tileBF(uint32_t sdst, const __half* g, size_t ld,
                                            int tid) {
    #pragma unroll
    for (int j = 0; j < 2; ++j) {
        int idx = tid + j * 256;
        int r = idx >> 4, c = idx & 15;
        CP_ASYNC(sdst + (r * BSTR_F + c * 8) * 2, g + (size_t)r * ld + c * 8);
    }
}
__device__ __forceinline__ void load_tileBD(uint32_t sdst, const __half* g, size_t ld,
                                            int tid) {
    #pragma unroll
    for (int j = 0; j < 4; ++j) {
        int idx = tid + j * 256;
        int r = idx >> 5, c = idx & 31;
        CP_ASYNC(sdst + (r * BSTR_D + c * 8) * 2, g + (size_t)r * ld + c * 8);
    }
}

// ---------------------------------------------------------------------------
// Exact tile cover: linear m-tile id -> (expert, start, cnt, m0).
// ---------------------------------------------------------------------------
__device__ __forceinline__ bool map_tile(const int* __restrict__ tpe, int t,
                                         int& e, int& start, int& cnt, int& m0) {
    int rem = t, st = 0;
    #pragma unroll
    for (int i = 0; i < NEXP; ++i) {
        const int c = __ldg(&tpe[i]);
        const int nt = (c + 127) >> 7;
        if (rem < nt) { e = i; start = st; cnt = c; m0 = rem << 7; return true; }
        rem -= nt;
        st += c;
    }
    return false;
}

// ---------------------------------------------------------------------------
// Fused gate/up compute stage (R9/R14, unchanged)
// ---------------------------------------------------------------------------
__device__ __forceinline__ void compute_stage_fused(
    uint32_t sbase, uint32_t aOff, uint32_t bOff,
    float cg[4][4][4], float cu[4][4][4])
{
    const uint32_t aA = sbase + aOff;
    const uint32_t aG = sbase + TA_BYTES + bOff;
    const uint32_t aU = aG + BF_BYTES;
    #pragma unroll
    for (int ks = 0; ks < 2; ++ks) {
        uint32_t a[4][4];
        #pragma unroll
        for (int mt = 0; mt < 4; ++mt)
            ldm_x4(a[mt][0], a[mt][1], a[mt][2], a[mt][3], aA + ks * 32 + mt * 1280);
        uint32_t bg[4][2], bu[4][2];
        const uint32_t ksb = ks * 16 * BSTR_F * 2;
        #pragma unroll
        for (int p = 0; p < 2; ++p) {
            ldm_x4_trans(bg[2*p][0], bg[2*p][1], bg[2*p+1][0], bg[2*p+1][1],
                         aG + ksb + p * 32);
            ldm_x4_trans(bu[2*p][0], bu[2*p][1], bu[2*p+1][0], bu[2*p+1][1],
                         aU + ksb + p * 32);
        }
        #pragma unroll
        for (int mt = 0; mt < 4; ++mt)
            #pragma unroll
            for (int nt = 0; nt < 4; ++nt) {
                mma_f16(cg[mt][nt], a[mt], bg[nt]);
                mma_f16(cu[mt][nt], a[mt], bu[nt]);
            }
    }
}

// ---------------------------------------------------------------------------
// Fused gate/up GEMM + SwiGLU with tail-gated down-weight conversion.
// Grid (INTER_/128, tcover); padding CTAs fall straight into the tail path.
// ---------------------------------------------------------------------------
__global__ __launch_bounds__(256, 1)
void fused_gate_up(const __half* __restrict__ X, const __half* __restrict__ WG,
                   const __half* __restrict__ WU, __half* __restrict__ OUT,
                   const int* __restrict__ tpe,
                   const float* __restrict__ down_raw)
{
    const int tid = threadIdx.x;
    extern __shared__ __half sm[];

    int e, start, cnt, m0;
    const bool valid = map_tile(tpe, blockIdx.y, e, start, cnt, m0);

    if (valid) {
        const int rows = min(128, cnt - m0);
        const int n0 = blockIdx.x * 128;

        const uint32_t sb = smem_u32(sm);
        const int wid = tid >> 5, lane = tid & 31;
        const int wm = wid & 1, wn = wid >> 1;

        const __half* Ag = X  + (size_t)(start + m0) * HID;
        const __half* Gg = WG + (size_t)e * HI + n0;     // [K=H][N=I]
        const __half* Ug = WU + (size_t)e * HI + n0;

        const uint32_t aOff = ((wm * 64 + (lane & 15)) * ASTRIDE + (lane >> 4) * 8) * 2;
        const uint32_t bRow = ((lane >> 3) & 1) * 8 + (lane & 7);
        const uint32_t bOff = (bRow * BSTR_F + wn * 32 + (lane >> 4) * 8) * 2;

        float cg[4][4][4], cu[4][4][4];
        #pragma unroll
        for (int a = 0; a < 4; ++a)
            #pragma unroll
            for (int b = 0; b < 4; ++b)
                #pragma unroll
                for (int c = 0; c < 4; ++c) { cg[a][b][c] = 0.f; cu[a][b][c] = 0.f; }

        const int niter = HID / BK;  // 32
        #pragma unroll
        for (int s = 0; s < STAGES - 1; ++s) {
            const uint32_t st = sb + s * FS_STAGE;
            load_tileA (st,                       Ag + s * BK, HID, tid, rows);
            load_tileBF(st + TA_BYTES,            Gg + (size_t)s * BK * INTER_, INTER_, tid);
            load_tileBF(st + TA_BYTES + BF_BYTES, Ug + (size_t)s * BK * INTER_, INTER_, tid);
            CP_COMMIT();
        }
        for (int i = 0; i < niter; ++i) {
            CP_WAIT2();
            __syncthreads();
            compute_stage_fused(sb + (i % STAGES) * FS_STAGE, aOff, bOff, cg, cu);
            const int nb = i + STAGES - 1;
            if (nb < niter) {
                const uint32_t st = sb + (nb % STAGES) * FS_STAGE;
                load_tileA (st,                       Ag + nb * BK, HID, tid, rows);
                load_tileBF(st + TA_BYTES,            Gg + (size_t)nb * BK * INTER_, INTER_, tid);
                load_tileBF(st + TA_BYTES + BF_BYTES, Ug + (size_t)nb * BK * INTER_, INTER_, tid);
            }
            CP_COMMIT();
        }

        // Epilogue: SwiGLU, fp16 RN, packed stores
        const int rbase = wm * 64 + (lane >> 2);
        const int cbase = n0 + wn * 32 + 2 * (lane & 3);
        #pragma unroll
        for (int mt = 0; mt < 4; ++mt) {
            #pragma unroll
            for (int nt = 0; nt < 4; ++nt) {
                const int r0 = rbase + mt * 16;
                const int c  = cbase + nt * 8;
                if (r0 < rows) {
                    float a0 = cg[mt][nt][0], a1 = cg[mt][nt][1];
                    uint32_t v = f22u(a0 / (1.f + __expf(-a0)) * cu[mt][nt][0],
                                      a1 / (1.f + __expf(-a1)) * cu[mt][nt][1]);
                    *(uint32_t*)(OUT + (size_t)(start + m0 + r0) * INTER_ + c) = v;
                }
                if (r0 + 8 < rows) {
                    float a2 = cg[mt][nt][2], a3 = cg[mt][nt][3];
                    uint32_t v = f22u(a2 / (1.f + __expf(-a2)) * cu[mt][nt][2],
                                      a3 / (1.f + __expf(-a3)) * cu[mt][nt][3]);
                    *(uint32_t*)(OUT + (size_t)(start + m0 + r0 + 8) * INTER_ + c) = v;
                }
            }
        }
    }

    // ---- Tail-gated down-weight conversion (work-stealing) ----
    // Only CTAs whose completion leaves < 148 unfinished CTAs may convert,
    // so no queued GEMM CTA is ever delayed (R13 lesson). Padding CTAs are
    // scheduled last, qualify immediately, and become free converters.
    __shared__ int s_tok;
    const int total = (int)(gridDim.x * gridDim.y);
    if (tid == 0) s_tok = atomicAdd(&g_flags[1], 1);
    __syncthreads();
    if (s_tok < total - NQ_TAIL) return;

    for (;;) {
        if (tid == 0) s_tok = atomicAdd(&g_flags[0], 1);
        __syncthreads();
        const int c = s_tok;
        __syncthreads();                       // s_tok reusable next iter
        if (c >= NCHUNK) return;
        const float4* in = (const float4*)(down_raw + (size_t)c * CHUNK_FL);
        uint4* out = (uint4*)(g_wd + (size_t)c * CHUNK_FL);
        #pragma unroll 4
        for (int j = 0; j < 16; ++j) {         // 4096 uint4 outs, 16/thread
            const int idx = tid + j * 256;
            float4 a = in[2 * idx], b = in[2 * idx + 1];
            uint4 v;
            v.x = f22u(a.x, a.y); v.y = f22u(a.z, a.w);
            v.z = f22u(b.x, b.y); v.w = f22u(b.z, b.w);
            out[idx] = v;
        }
    }
}

// ---------------------------------------------------------------------------
// Down-proj GEMM (R14, unchanged): out(fp32) = inter @ down.
// ---------------------------------------------------------------------------
__device__ __forceinline__ void compute_stage_down(
    uint32_t sbase, uint32_t aOff, uint32_t bOff, float cc[4][8][4])
{
    const uint32_t aA = sbase + aOff;
    const uint32_t aB = sbase + TA_BYTES + bOff;
    #pragma unroll
    for (int ks = 0; ks < 2; ++ks) {
        uint32_t a[4][4];
        #pragma unroll
        for (int mt = 0; mt < 4; ++mt)
            ldm_x4(a[mt][0], a[mt][1], a[mt][2], a[mt][3], aA + ks * 32 + mt * 1280);
        uint32_t bf[8][2];
        const uint32_t ksb = ks * 16 * BSTR_D * 2;
        #pragma unroll
        for (int p = 0; p < 4; ++p)
            ldm_x4_trans(bf[2*p][0], bf[2*p][1], bf[2*p+1][0], bf[2*p+1][1],
                         aB + ksb + p * 32);
        #pragma unroll
        for (int mt = 0; mt < 4; ++mt)
            #pragma unroll
            for (int nt = 0; nt < 8; ++nt)
                mma_f16(cc[mt][nt], a[mt], bf[nt]);
    }
}

__global__ __launch_bounds__(256, 1)
void down_proj(const __half* __restrict__ X, const __half* __restrict__ WD,
               float* __restrict__ OUT, const int* __restrict__ tpe)
{
    int e, start, cnt, m0;
    if (!map_tile(tpe, blockIdx.x, e, start, cnt, m0)) return;
    const int rows = min(128, cnt - m0);
    const int n0 = blockIdx.y * 256;

    extern __shared__ __half sm[];
    const uint32_t sb = smem_u32(sm);
    const int tid = threadIdx.x, wid = tid >> 5, lane = tid & 31;
    const int wm = wid & 1, wn = wid >> 1;

    const __half* Ag = X  + (size_t)(start + m0) * INTER_;
    const __half* Bg = WD + (size_t)e * HI + n0;

    const uint32_t aOff = ((wm * 64 + (lane & 15)) * ASTRIDE + (lane >> 4) * 8) * 2;
    const uint32_t bRow = ((lane >> 3) & 1) * 8 + (lane & 7);
    const uint32_t bOff = (bRow * BSTR_D + wn * 64 + (lane >> 4) * 8) * 2;

    float cc[4][8][4];
    #pragma unroll
    for (int a = 0; a < 4; ++a)
        #pragma unroll
        for (int b = 0; b < 8; ++b)
            #pragma unroll
            for (int c = 0; c < 4; ++c) cc[a][b][c] = 0.f;

    const int niter = INTER_ / BK;  // 88
    #pragma unroll
    for (int s = 0; s < STAGES - 1; ++s) {
        const uint32_t st = sb + s * DS_STAGE;
        load_tileA (st,            Ag + s * BK, INTER_, tid, rows);
        load_tileBD(st + TA_BYTES, Bg + (size_t)s * BK * HID, HID, tid);
        CP_COMMIT();
    }
    for (int i = 0; i < niter; ++i) {
        CP_WAIT2();
        __syncthreads();
        compute_stage_down(sb + (i % STAGES) * DS_STAGE, aOff, bOff, cc);
        const int nb = i + STAGES - 1;
        if (nb < niter) {
            const uint32_t st = sb + (nb % STAGES) * DS_STAGE;
            load_tileA (st,            Ag + nb * BK, INTER_, tid, rows);
            load_tileBD(st + TA_BYTES, Bg + (size_t)nb * BK * HID, HID, tid);
        }
        CP_COMMIT();
    }

    const int rbase = wm * 64 + (lane >> 2);
    const int cbase = n0 + wn * 64 + 2 * (lane & 3);
    #pragma unroll
    for (int mt = 0; mt < 4; ++mt) {
        #pragma unroll
        for (int nt = 0; nt < 8; ++nt) {
            const int r0 = rbase + mt * 16;
            const int c  = cbase + nt * 8;
            if (r0 < rows) {
                float2 v = make_float2(cc[mt][nt][0], cc[mt][nt][1]);
                *reinterpret_cast<float2*>(OUT + (size_t)(start + m0 + r0) * HID + c) = v;
            }
            if (r0 + 8 < rows) {
                float2 v = make_float2(cc[mt][nt][2], cc[mt][nt][3]);
                *reinterpret_cast<float2*>(OUT + (size_t)(start + m0 + r0 + 8) * HID + c) = v;
            }
        }
    }
}

// ---------------------------------------------------------------------------
// Host side: single stream, three plain launches.
// ---------------------------------------------------------------------------
extern "C" void kernel_launch(void* const* d_in, const int* in_sizes, int n_in,
                              void* d_out, int out_size)
{
    const float* x    = (const float*)d_in[0];   // [T, H]
    const float* gate = (const float*)d_in[1];   // [E, H, I]
    const float* up   = (const float*)d_in[2];   // [E, H, I]
    const float* down = (const float*)d_in[3];   // [E, I, H]
    const int*   tpe  = (const int*)d_in[4];     // [E]
    float* out = (float*)d_out;                  // [T, H]

    const int T = in_sizes[0] / HID;

    __half *xh, *wg, *wu, *wd, *inter;
    cudaGetSymbolAddress((void**)&xh, g_xh);
    cudaGetSymbolAddress((void**)&wg, g_wg);
    cudaGetSymbolAddress((void**)&wu, g_wu);
    cudaGetSymbolAddress((void**)&wd, g_wd);
    cudaGetSymbolAddress((void**)&inter, g_inter);

    cudaFuncSetAttribute(fused_gate_up, cudaFuncAttributeMaxDynamicSharedMemorySize,
                         STAGES * FS_STAGE);
    cudaFuncSetAttribute(down_proj, cudaFuncAttributeMaxDynamicSharedMemorySize,
                         STAGES * DS_STAGE);

    // 1) Pre-pass: convert x, gate, up (down is converted in the fused tail).
    cvt_xgu_kernel<<<dim3(4096, 3), 256>>>(x, gate, up, T);

    // 2) Fused gate/up GEMM + SwiGLU + tail-gated down conversion.
    const int tcover = (T + 127) / 128 + NEXP;
    dim3 g1(INTER_ / 128, tcover);
    fused_gate_up<<<g1, 256, STAGES * FS_STAGE>>>(xh, wg, wu, inter, tpe, down);

    // 3) Down projection (down weights ready at the kernel boundary).
    dim3 g2(tcover, HID / 256);
    down_proj<<<g2, 256, STAGES * DS_STAGE>>>(inter, wd, out, tpe);
}